// round 3
// baseline (speedup 1.0000x reference)
#include <cuda_runtime.h>
#include <math.h>

#define N_PTS   131072
#define WIDTH   256
#define P       16          // points per CTA
#define THREADS 512         // 16 warps: warp = (point-pair) x (128-col half)
#define KT      32          // K tile for W streaming
#define AROW    96          // floats per k-row of As: 8 pairs * 12
                            // As[k][pp][c][e], e = point-in-pair

#define SMEM_A_FLOATS (WIDTH * AROW)       // 24576 (96KB)
#define SMEM_B_FLOATS (2 * KT * WIDTH)     // 16384 (64KB)
#define SMEM_BYTES   ((SMEM_A_FLOATS + SMEM_B_FLOATS) * 4)  // 163840

typedef unsigned long long u64;

__device__ __forceinline__ float fast_tanh(float x) {
    float e = __expf(2.0f * x);
    return 1.0f - __fdividef(2.0f, e + 1.0f);
}
__device__ __forceinline__ u64 pack2(float a) {            // {a,a}
    u64 r; asm("mov.b64 %0, {%1, %1};" : "=l"(r) : "f"(a)); return r;
}
__device__ __forceinline__ u64 packpair(float a, float b) { // {a,b}
    u64 r; asm("mov.b64 %0, {%1, %2};" : "=l"(r) : "f"(a), "f"(b)); return r;
}
__device__ __forceinline__ void ffma2(u64& acc, u64 a, u64 b) {
    asm("fma.rn.f32x2 %0, %1, %2, %0;" : "+l"(acc) : "l"(a), "l"(b));
}
__device__ __forceinline__ float2 unpack2(u64 v) {
    float2 f; asm("mov.b64 {%0, %1}, %2;" : "=f"(f.x), "=f"(f.y) : "l"(v)); return f;
}

__global__ void __launch_bounds__(THREADS, 1)
pde_kernel(const float* __restrict__ xyt,
           const float* __restrict__ w0, const float* __restrict__ b0,
           const float* __restrict__ w1, const float* __restrict__ b1,
           const float* __restrict__ w2, const float* __restrict__ b2,
           const float* __restrict__ w3, const float* __restrict__ b3,
           const float* __restrict__ w4, const float* __restrict__ b4,
           const float* __restrict__ w5, const float* __restrict__ b5,
           const float* __restrict__ w6, const float* __restrict__ b6,
           float* __restrict__ out)
{
    extern __shared__ float smem[];
    float* As = smem;                      // [256][8 pairs][6 ch][2 pts]
    float* Bs = smem + SMEM_A_FLOATS;      // [2][KT][256]

    const int t   = threadIdx.x;
    const int w   = t >> 5;
    const int g   = t & 31;
    const int pp  = w & 7;                 // point-pair id (0..7)
    const int ch2 = w >> 3;                // column half (0/1)
    const int colbase = 128 * ch2 + 4 * g; // 4 consecutive cols per lane

    // the warp's two global points
    const int pg0 = blockIdx.x * P + 2 * pp;
    float px[2], py[2], ptm[2];
    #pragma unroll
    for (int e = 0; e < 2; e++) {
        px[e]  = xyt[3 * (pg0 + e) + 0];
        py[e]  = xyt[3 * (pg0 + e) + 1];
        ptm[e] = xyt[3 * (pg0 + e) + 2];
    }

    float* Apair = As + pp * 12;           // + col*AROW + 2*c + e

    // ---------------- Layer 0: 3 -> 256 + tanh -----------------------------
    #pragma unroll
    for (int q = 0; q < 4; q++) {
        int j = colbase + q;
        float wx = w0[j];
        float wy = w0[WIDTH + j];
        float wt = w0[2 * WIDTH + j];
        float bj = b0[j];
        float* r = Apair + j * AROW;
        #pragma unroll
        for (int e = 0; e < 2; e++) {
            float z = fmaf(px[e], wx, fmaf(py[e], wy, fmaf(ptm[e], wt, bj)));
            float v = fast_tanh(z);
            float s = 1.0f - v * v;
            r[0 + e]  = v;
            r[2 + e]  = s * wx;
            r[4 + e]  = s * wy;
            r[6 + e]  = s * wt;
            r[8 + e]  = -2.0f * v * s * wx * wx;
            r[10 + e] = -2.0f * v * s * wy * wy;
        }
    }
    __syncthreads();

    const float* Ws[5]  = { w1, w2, w3, w4, w5 };
    const float* Bbs[5] = { b1, b2, b3, b4, b5 };

    // ---------------- Layers 1..5 ------------------------------------------
    for (int l = 0; l < 5; l++) {
        const float* W = Ws[l];

        // acc2[c][q]: packed {pt0, pt1} for channel c, column colbase+q
        u64 acc2[6][4];
        #pragma unroll
        for (int c = 0; c < 6; c++)
            #pragma unroll
            for (int q = 0; q < 4; q++) acc2[c][q] = 0ull;

        float4 rb[4];
        {
            const float4* Wv = (const float4*)W;
            #pragma unroll
            for (int i = 0; i < 4; i++) rb[i] = Wv[t + THREADS * i];
        }

        int buf = 0;
        for (int kt = 0; kt < WIDTH / KT; kt++) {
            float4* bsv = (float4*)(Bs + buf * KT * WIDTH);
            #pragma unroll
            for (int i = 0; i < 4; i++) bsv[t + THREADS * i] = rb[i];
            __syncthreads();

            if (kt < WIDTH / KT - 1) {
                const float4* Wn = (const float4*)(W + (kt + 1) * KT * WIDTH);
                #pragma unroll
                for (int i = 0; i < 4; i++) rb[i] = Wn[t + THREADS * i];
            }

            const float* Ak   = As + (kt * KT) * AROW + pp * 12;
            const float* Brow = Bs + buf * KT * WIDTH + colbase;

            #pragma unroll 4
            for (int k = 0; k < KT; k++) {
                // A: 12 contiguous floats = 3 broadcast LDS.128 -> 6 packed u64
                ulonglong2 a01 = *(const ulonglong2*)(Ak);
                ulonglong2 a23 = *(const ulonglong2*)(Ak + 4);
                ulonglong2 a45 = *(const ulonglong2*)(Ak + 8);
                Ak += AROW;
                u64 ap[6] = { a01.x, a01.y, a23.x, a23.y, a45.x, a45.y };

                // B: 4 cols per lane, one LDS.128, then duplicate each lane
                float4 b = *(const float4*)(Brow + k * WIDTH);
                u64 bd[4] = { pack2(b.x), pack2(b.y), pack2(b.z), pack2(b.w) };

                #pragma unroll
                for (int c = 0; c < 6; c++)
                    #pragma unroll
                    for (int q = 0; q < 4; q++)
                        ffma2(acc2[c][q], ap[c], bd[q]);
            }
            buf ^= 1;
        }
        __syncthreads();   // all reads of As done before overwrite

        const float* bias = Bbs[l];
        #pragma unroll
        for (int q = 0; q < 4; q++) {
            int j = colbase + q;
            float bj = bias[j];
            float2 au   = unpack2(acc2[0][q]);
            float2 aux  = unpack2(acc2[1][q]);
            float2 auy  = unpack2(acc2[2][q]);
            float2 aut  = unpack2(acc2[3][q]);
            float2 auxx = unpack2(acc2[4][q]);
            float2 auyy = unpack2(acc2[5][q]);
            float vv[2], vx[2], vy[2], vt_[2], vxx[2], vyy[2];
            #pragma unroll
            for (int e = 0; e < 2; e++) {
                float u   = (e ? au.y   : au.x) + bj;
                float ux  = (e ? aux.y  : aux.x);
                float uy  = (e ? auy.y  : auy.x);
                float ut  = (e ? aut.y  : aut.x);
                float uxx = (e ? auxx.y : auxx.x);
                float uyy = (e ? auyy.y : auyy.x);
                float v = fast_tanh(u);
                float s = 1.0f - v * v;
                float tvs = 2.0f * v * s;
                vv[e]  = v;
                vx[e]  = s * ux;
                vy[e]  = s * uy;
                vt_[e] = s * ut;
                vxx[e] = fmaf(s, uxx, -tvs * ux * ux);
                vyy[e] = fmaf(s, uyy, -tvs * uy * uy);
            }
            u64* r = (u64*)(Apair + j * AROW);   // 8B-aligned (48B pair stride)
            r[0] = packpair(vv[0],  vv[1]);
            r[1] = packpair(vx[0],  vx[1]);
            r[2] = packpair(vy[0],  vy[1]);
            r[3] = packpair(vt_[0], vt_[1]);
            r[4] = packpair(vxx[0], vxx[1]);
            r[5] = packpair(vyy[0], vyy[1]);
        }
        __syncthreads();
    }

    // ---------------- Layer 6: 256 -> 1, packed reduction -------------------
    u64 acc6[6] = {0ull, 0ull, 0ull, 0ull, 0ull, 0ull};
    #pragma unroll
    for (int q = 0; q < 4; q++) {
        int j = colbase + q;
        u64 wvd = pack2(w6[j]);
        const ulonglong2* r = (const ulonglong2*)(Apair + j * AROW);
        ulonglong2 a01 = r[0], a23 = r[1], a45 = r[2];
        ffma2(acc6[0], a01.x, wvd);
        ffma2(acc6[1], a01.y, wvd);
        ffma2(acc6[2], a23.x, wvd);
        ffma2(acc6[3], a23.y, wvd);
        ffma2(acc6[4], a45.x, wvd);
        ffma2(acc6[5], a45.y, wvd);
    }
    #pragma unroll
    for (int off = 16; off > 0; off >>= 1) {
        #pragma unroll
        for (int c = 0; c < 6; c++) {
            float2 f = unpack2(acc6[c]);
            f.x += __shfl_xor_sync(0xFFFFFFFFu, f.x, off);
            f.y += __shfl_xor_sync(0xFFFFFFFFu, f.y, off);
            acc6[c] = packpair(f.x, f.y);
        }
    }

    // partials: red[pt 0..15][ch2][c]  (lives in Bs region, disjoint from As)
    float* red = Bs;
    if (g == 0) {
        #pragma unroll
        for (int c = 0; c < 6; c++) {
            float2 f = unpack2(acc6[c]);
            red[(2 * pp + 0) * 12 + ch2 * 6 + c] = f.x;
            red[(2 * pp + 1) * 12 + ch2 * 6 + c] = f.y;
        }
    }
    __syncthreads();

    if (t < P) {
        int pg = blockIdx.x * P + t;
        float h   = red[t * 12 + 0] + red[t * 12 + 6]  + b6[0];
        float hx  = red[t * 12 + 1] + red[t * 12 + 7];
        float hy  = red[t * 12 + 2] + red[t * 12 + 8];
        float ht  = red[t * 12 + 3] + red[t * 12 + 9];
        float hxx = red[t * 12 + 4] + red[t * 12 + 10];
        float hyy = red[t * 12 + 5] + red[t * 12 + 11];
        float xx = xyt[3 * pg + 0];
        float yy = xyt[3 * pg + 1];
        float tt = xyt[3 * pg + 2];
        const float PI = 3.14159265358979323846f;
        float f = sinf(PI * xx) * sinf(PI * yy) * expf(-tt);
        out[pg] = ht - 0.5f * (h * (hxx + hyy) + hx * hx + hy * hy) - f;
    }
}

extern "C" void kernel_launch(void* const* d_in, const int* in_sizes, int n_in,
                              void* d_out, int out_size)
{
    const float* xyt = (const float*)d_in[0];
    const float* w0  = (const float*)d_in[1];
    const float* b0  = (const float*)d_in[2];
    const float* w1  = (const float*)d_in[3];
    const float* b1  = (const float*)d_in[4];
    const float* w2  = (const float*)d_in[5];
    const float* b2  = (const float*)d_in[6];
    const float* w3  = (const float*)d_in[7];
    const float* b3  = (const float*)d_in[8];
    const float* w4  = (const float*)d_in[9];
    const float* b4  = (const float*)d_in[10];
    const float* w5  = (const float*)d_in[11];
    const float* b5  = (const float*)d_in[12];
    const float* w6  = (const float*)d_in[13];
    const float* b6  = (const float*)d_in[14];

    cudaFuncSetAttribute(pde_kernel,
                         cudaFuncAttributeMaxDynamicSharedMemorySize,
                         SMEM_BYTES);

    dim3 grid(N_PTS / P);
    pde_kernel<<<grid, THREADS, SMEM_BYTES>>>(
        xyt, w0, b0, w1, b1, w2, b2, w3, b3, w4, b4, w5, b5, w6, b6,
        (float*)d_out);
}

// round 7
// speedup vs baseline: 1.1846x; 1.1846x over previous
#include <cuda_runtime.h>
#include <math.h>

#define N_PTS   131072
#define WIDTH   256
#define P       16              // points per CTA, warp = point
#define THREADS 512
#define KT      32              // K tile rows
#define NT_LAYER 8              // 256/32 tiles per layer
#define N_TILES  40             // 5 hidden layers * 8
#define AS_PT   (WIDTH * 6)     // 1536 floats per point: [j][ch]
#define AS_FLOATS (P * AS_PT)   // 24576
#define BT_FLOATS (KT * WIDTH)  // 8192 floats per tile
#define B_FLOATS  (3 * BT_FLOATS)
#define SMEM_BYTES ((AS_FLOATS + B_FLOATS) * 4 + 128)   // 196736

typedef unsigned long long u64;

__device__ __forceinline__ float fast_tanh(float x) {
    float e = __expf(2.0f * x);
    return 1.0f - __fdividef(2.0f, e + 1.0f);
}
__device__ __forceinline__ u64 pack2(float a) {              // {a,a}
    u64 r; asm("mov.b64 %0, {%1, %1};" : "=l"(r) : "f"(a)); return r;
}
__device__ __forceinline__ u64 packpair(float a, float b) {  // {a,b}
    u64 r; asm("mov.b64 %0, {%1, %2};" : "=l"(r) : "f"(a), "f"(b)); return r;
}
__device__ __forceinline__ void ffma2(u64& acc, u64 a, u64 b) {
    asm("fma.rn.f32x2 %0, %1, %2, %0;" : "+l"(acc) : "l"(a), "l"(b));
}
__device__ __forceinline__ float2 unpack2(u64 v) {
    float2 f; asm("mov.b64 {%0, %1}, %2;" : "=f"(f.x), "=f"(f.y) : "l"(v)); return f;
}

// stage one 32x256 W tile into the 3-deep smem ring via cp.async (.cg: L2 only)
__device__ __forceinline__ void issue_tile(const float* const* shW,
                                           float* Bs, int gt, int t) {
    const float* src = shW[gt >> 3] + (gt & 7) * BT_FLOATS;
    float* dst = Bs + (gt % 3) * BT_FLOATS;
    #pragma unroll
    for (int c = 0; c < 4; c++) {
        int idx = (t + THREADS * c) * 4;             // float index, 16B chunks
        unsigned saddr = (unsigned)__cvta_generic_to_shared(dst + idx);
        asm volatile("cp.async.cg.shared.global [%0], [%1], 16;"
                     :: "r"(saddr), "l"(src + idx));
    }
    asm volatile("cp.async.commit_group;" ::: "memory");
}

__global__ void __launch_bounds__(THREADS, 1)
pde_kernel(const float* __restrict__ xyt,
           const float* __restrict__ w0, const float* __restrict__ b0,
           const float* __restrict__ w1, const float* __restrict__ b1,
           const float* __restrict__ w2, const float* __restrict__ b2,
           const float* __restrict__ w3, const float* __restrict__ b3,
           const float* __restrict__ w4, const float* __restrict__ b4,
           const float* __restrict__ w5, const float* __restrict__ b5,
           const float* __restrict__ w6, const float* __restrict__ b6,
           float* __restrict__ out)
{
    extern __shared__ float smem[];
    float* As = smem;                               // [P][256][6] warp-private
    float* Bs = smem + AS_FLOATS;                   // [3][KT][256]
    const float** shW = (const float**)(smem + AS_FLOATS + B_FLOATS); // 10 ptrs

    const int t  = threadIdx.x;
    const int p  = t >> 5;
    const int g  = t & 31;
    const int pg = blockIdx.x * P + p;

    if (t == 0) {
        shW[0] = w1; shW[1] = w2; shW[2] = w3; shW[3] = w4; shW[4] = w5;
        shW[5] = b1; shW[6] = b2; shW[7] = b3; shW[8] = b4; shW[9] = b5;
    }
    __syncthreads();

    // start the W pipeline: tiles 0,1 of layer 1 in flight during layer 0
    issue_tile(shW, Bs, 0, t);
    issue_tile(shW, Bs, 1, t);

    const float x  = xyt[3 * pg + 0];
    const float y  = xyt[3 * pg + 1];
    const float tm = xyt[3 * pg + 2];

    float* Ap = As + p * AS_PT;                     // this warp's block

    // ---------------- Layer 0: 3 -> 256 + tanh (warp-private) -------------
    #pragma unroll
    for (int m = 0; m < 4; m++) {
        #pragma unroll
        for (int e = 0; e < 2; e++) {
            int j = 2 * g + 64 * m + e;
            float wx = w0[j];
            float wy = w0[WIDTH + j];
            float wt = w0[2 * WIDTH + j];
            float z  = fmaf(x, wx, fmaf(y, wy, fmaf(tm, wt, b0[j])));
            float v  = fast_tanh(z);
            float s  = 1.0f - v * v;
            float* r = Ap + j * 6;
            r[0] = v;
            r[1] = s * wx;
            r[2] = s * wy;
            r[3] = s * wt;
            r[4] = -2.0f * v * s * wx * wx;
            r[5] = -2.0f * v * s * wy * wy;
        }
    }
    __syncwarp();

    // ---------------- Layers 1..5 -----------------------------------------
    for (int l = 0; l < 5; l++) {
        u64 acc2[6][4];
        #pragma unroll
        for (int c = 0; c < 6; c++)
            #pragma unroll
            for (int m = 0; m < 4; m++) acc2[c][m] = 0ull;

        for (int ti = 0; ti < NT_LAYER; ti++) {
            const int gt = l * NT_LAYER + ti;
            if (gt < N_TILES - 1)
                asm volatile("cp.async.wait_group 1;" ::: "memory");
            else
                asm volatile("cp.async.wait_group 0;" ::: "memory");
            __syncthreads();                         // tile gt visible; buf (gt+2)%3 free
            if (gt + 2 < N_TILES) issue_tile(shW, Bs, gt + 2, t);

            const float* Bbase = Bs + (gt % 3) * BT_FLOATS + 2 * g;
            const float* Ak    = Ap + (ti * KT) * 6;

            #pragma unroll 8
            for (int k = 0; k < KT; k++) {
                u64 ad[6];
                #pragma unroll
                for (int c = 0; c < 6; c++) ad[c] = pack2(Ak[c]); // scalar bcast
                Ak += 6;
                const float* br = Bbase + k * WIDTH;
                #pragma unroll
                for (int m = 0; m < 4; m++) {
                    u64 bv = *(const u64*)(br + 64 * m);  // {b_j,b_j+1}
                    #pragma unroll
                    for (int c = 0; c < 6; c++)
                        ffma2(acc2[c][m], ad[c], bv);
                }
            }
        }

        // epilogue: warp-private, no block sync
        const float* bias = shW[5 + l];
        #pragma unroll
        for (int m = 0; m < 4; m++) {
            float2 au   = unpack2(acc2[0][m]);
            float2 aux  = unpack2(acc2[1][m]);
            float2 auy  = unpack2(acc2[2][m]);
            float2 aut  = unpack2(acc2[3][m]);
            float2 auxx = unpack2(acc2[4][m]);
            float2 auyy = unpack2(acc2[5][m]);
            #pragma unroll
            for (int e = 0; e < 2; e++) {
                int j = 2 * g + 64 * m + e;
                float u   = (e ? au.y   : au.x) + bias[j];
                float ux  = (e ? aux.y  : aux.x);
                float uy  = (e ? auy.y  : auy.x);
                float ut  = (e ? aut.y  : aut.x);
                float uxx = (e ? auxx.y : auxx.x);
                float uyy = (e ? auyy.y : auyy.x);
                float v = fast_tanh(u);
                float s = 1.0f - v * v;
                float tvs = 2.0f * v * s;
                u64* r = (u64*)(Ap + j * 6);          // 8B aligned (24j bytes)
                r[0] = packpair(v,      s * ux);
                r[1] = packpair(s * uy, s * ut);
                r[2] = packpair(fmaf(s, uxx, -tvs * ux * ux),
                                fmaf(s, uyy, -tvs * uy * uy));
            }
        }
        __syncwarp();
    }

    // ---------------- Layer 6: 256 -> 1, pure warp reduction ---------------
    float h = 0.f, hx = 0.f, hy = 0.f, ht = 0.f, hxx = 0.f, hyy = 0.f;
    #pragma unroll
    for (int m = 0; m < 4; m++) {
        #pragma unroll
        for (int e = 0; e < 2; e++) {
            int j = 2 * g + 64 * m + e;
            float wv = w6[j];
            const float* r = Ap + j * 6;
            h   = fmaf(r[0], wv, h);
            hx  = fmaf(r[1], wv, hx);
            hy  = fmaf(r[2], wv, hy);
            ht  = fmaf(r[3], wv, ht);
            hxx = fmaf(r[4], wv, hxx);
            hyy = fmaf(r[5], wv, hyy);
        }
    }
    #pragma unroll
    for (int off = 16; off > 0; off >>= 1) {
        h   += __shfl_xor_sync(0xFFFFFFFFu, h,   off);
        hx  += __shfl_xor_sync(0xFFFFFFFFu, hx,  off);
        hy  += __shfl_xor_sync(0xFFFFFFFFu, hy,  off);
        ht  += __shfl_xor_sync(0xFFFFFFFFu, ht,  off);
        hxx += __shfl_xor_sync(0xFFFFFFFFu, hxx, off);
        hyy += __shfl_xor_sync(0xFFFFFFFFu, hyy, off);
    }

    if (g == 0) {
        h += b6[0];
        const float PI = 3.14159265358979323846f;
        float f = sinf(PI * x) * sinf(PI * y) * expf(-tm);
        out[pg] = ht - 0.5f * (h * (hxx + hyy) + hx * hx + hy * hy) - f;
    }
}

extern "C" void kernel_launch(void* const* d_in, const int* in_sizes, int n_in,
                              void* d_out, int out_size)
{
    const float* xyt = (const float*)d_in[0];
    const float* w0  = (const float*)d_in[1];
    const float* b0  = (const float*)d_in[2];
    const float* w1  = (const float*)d_in[3];
    const float* b1  = (const float*)d_in[4];
    const float* w2  = (const float*)d_in[5];
    const float* b2  = (const float*)d_in[6];
    const float* w3  = (const float*)d_in[7];
    const float* b3  = (const float*)d_in[8];
    const float* w4  = (const float*)d_in[9];
    const float* b4  = (const float*)d_in[10];
    const float* w5  = (const float*)d_in[11];
    const float* b5  = (const float*)d_in[12];
    const float* w6  = (const float*)d_in[13];
    const float* b6  = (const float*)d_in[14];

    cudaFuncSetAttribute(pde_kernel,
                         cudaFuncAttributeMaxDynamicSharedMemorySize,
                         SMEM_BYTES);

    dim3 grid(N_PTS / P);
    pde_kernel<<<grid, THREADS, SMEM_BYTES>>>(
        xyt, w0, b0, w1, b1, w2, b2, w3, b3, w4, b4, w5, b5, w6, b6,
        (float*)d_out);
}